// round 2
// baseline (speedup 1.0000x reference)
#include <cuda_runtime.h>
#include <cstdint>

#define NMAX 50048
#define EMAX 800000
#define GPOOL 512
#define DOUTP 64
#define CHUNK 512
#define MAXCHUNK 128   // supports up to 65536 nodes

// ---------------- scratch (device globals; no allocation allowed) -------------
__device__ float g_h0[(size_t)NMAX * 128];
__device__ float g_h1[(size_t)NMAX * 128];
__device__ float g_dinv[NMAX];
__device__ int   g_cnt[NMAX];
__device__ int   g_cur[NMAX];
__device__ int   g_rowptr[NMAX + 1];
__device__ int   g_colidx[EMAX];
__device__ int   g_bsum[MAXCHUNK];
__device__ int   g_gcnt[GPOOL];

// ---------------- CSR build -------------------------------------------------
__global__ void k_zero(int* cnt, int* cur, int n) {
    int i = blockIdx.x * blockDim.x + threadIdx.x;
    if (i < n) { cnt[i] = 0; cur[i] = 0; }
}

__global__ void k_count(const int* __restrict__ ei, int* cnt, int E) {
    int e = blockIdx.x * blockDim.x + threadIdx.x;
    if (e < E) {
        int d = ei[E + e];
        atomicAdd(&cnt[d], 1);
    }
}

// per-chunk exclusive scan of cnt -> rowptr (local), chunk totals -> bsum; dinv too
__global__ void k_chunkscan(const int* __restrict__ cnt, int* rowptr, int* bsum,
                            float* dinv, int n) {
    __shared__ int sh[CHUNK];
    int tid = threadIdx.x;
    int i = blockIdx.x * CHUNK + tid;
    int v = (i < n) ? cnt[i] : 0;
    if (i < n) dinv[i] = rsqrtf((float)(v + 1));   // +1 for self loop
    sh[tid] = v;
    __syncthreads();
    for (int off = 1; off < CHUNK; off <<= 1) {
        int t = (tid >= off) ? sh[tid - off] : 0;
        __syncthreads();
        sh[tid] += t;
        __syncthreads();
    }
    if (i < n) rowptr[i] = sh[tid] - v;            // local exclusive
    if (tid == CHUNK - 1) bsum[blockIdx.x] = sh[tid];
}

// single-block scan of chunk totals (nb <= 128); also writes rowptr[n] = total
__global__ void k_bscan(int* bsum, int nb, int* rowptr, int n) {
    __shared__ int sh[MAXCHUNK];
    int tid = threadIdx.x;
    int v = (tid < nb) ? bsum[tid] : 0;
    sh[tid] = v;
    __syncthreads();
    for (int off = 1; off < MAXCHUNK; off <<= 1) {
        int t = (tid >= off) ? sh[tid - off] : 0;
        __syncthreads();
        sh[tid] += t;
        __syncthreads();
    }
    if (tid < nb) bsum[tid] = sh[tid] - v;         // exclusive
    if (tid == MAXCHUNK - 1) rowptr[n] = sh[tid];
}

__global__ void k_addoff(int* rowptr, const int* __restrict__ bsum, int n) {
    int i = blockIdx.x * blockDim.x + threadIdx.x;
    if (i < n) rowptr[i] += bsum[i / CHUNK];
}

__global__ void k_fill(const int* __restrict__ ei, int* cur,
                       const int* __restrict__ rowptr, int* colidx, int E) {
    int e = blockIdx.x * blockDim.x + threadIdx.x;
    if (e < E) {
        int s = ei[e];
        int d = ei[E + e];
        int pos = atomicAdd(&cur[d], 1);
        colidx[rowptr[d] + pos] = s;
    }
}

// ---------------- dense transform: C[n x BN] = A[n x 128] @ B[128 x BN] ------
template <int BN>
__global__ void k_gemm(const float* __restrict__ A, const float* __restrict__ B,
                       float* __restrict__ C, int n) {
    constexpr int BM = 64, BK = 32, K = 128;
    constexpr int TM = 4, TN = BN / 16;
    __shared__ float As[BK][BM + 1];
    __shared__ float Bs[BK][BN];
    int tid = threadIdx.x;
    int tx = tid & 15, ty = tid >> 4;
    int bm = blockIdx.x * BM;

    float acc[TM][TN];
#pragma unroll
    for (int i = 0; i < TM; i++)
#pragma unroll
        for (int j = 0; j < TN; j++) acc[i][j] = 0.f;

    for (int k0 = 0; k0 < K; k0 += BK) {
#pragma unroll
        for (int t = tid; t < BM * BK; t += 256) {
            int r = t >> 5, c = t & 31;
            int gr = bm + r;
            As[c][r] = (gr < n) ? A[(size_t)gr * K + k0 + c] : 0.f;
        }
#pragma unroll
        for (int t = tid; t < BK * BN; t += 256) {
            int r = t / BN, c = t % BN;
            Bs[r][c] = B[(size_t)(k0 + r) * BN + c];
        }
        __syncthreads();
#pragma unroll
        for (int kk = 0; kk < BK; kk++) {
            float a[TM], b[TN];
#pragma unroll
            for (int i = 0; i < TM; i++) a[i] = As[kk][ty * TM + i];
#pragma unroll
            for (int j = 0; j < TN; j++) b[j] = Bs[kk][tx + j * 16];
#pragma unroll
            for (int i = 0; i < TM; i++)
#pragma unroll
                for (int j = 0; j < TN; j++) acc[i][j] = fmaf(a[i], b[j], acc[i][j]);
        }
        __syncthreads();
    }
#pragma unroll
    for (int i = 0; i < TM; i++) {
        int gr = bm + ty * TM + i;
        if (gr < n) {
#pragma unroll
            for (int j = 0; j < TN; j++)
                C[(size_t)gr * BN + tx + j * 16] = acc[i][j];
        }
    }
}

// ---------------- fused normalized aggregation + bias (+relu) ----------------
// out[d] = relu( dinv[d]*( sum_s dinv[s]*h[s] + dinv[d]*h[d] ) + bias )
template <int D, bool RELU>
__global__ void k_agg(const float* __restrict__ hin, float* __restrict__ hout,
                      const float* __restrict__ dinv, const int* __restrict__ rowptr,
                      const int* __restrict__ colidx, const float* __restrict__ bias,
                      int n) {
    int warp = (blockIdx.x * blockDim.x + threadIdx.x) >> 5;
    int lane = threadIdx.x & 31;
    if (warp >= n) return;
    float di = dinv[warp];

    if constexpr (D == 128) {
        const float4* hp = (const float4*)(hin + (size_t)warp * 128) + lane;
        float4 v = *hp;
        float4 acc = make_float4(di * v.x, di * v.y, di * v.z, di * v.w);
        int beg = rowptr[warp], end = rowptr[warp + 1];
        for (int e = beg; e < end; e++) {
            int s = colidx[e];
            float ds = __ldg(&dinv[s]);
            float4 u = *((const float4*)(hin + (size_t)s * 128) + lane);
            acc.x += ds * u.x; acc.y += ds * u.y;
            acc.z += ds * u.z; acc.w += ds * u.w;
        }
        float4 bb = *((const float4*)bias + lane);
        float4 o;
        o.x = di * acc.x + bb.x; o.y = di * acc.y + bb.y;
        o.z = di * acc.z + bb.z; o.w = di * acc.w + bb.w;
        if (RELU) {
            o.x = fmaxf(o.x, 0.f); o.y = fmaxf(o.y, 0.f);
            o.z = fmaxf(o.z, 0.f); o.w = fmaxf(o.w, 0.f);
        }
        *((float4*)(hout + (size_t)warp * 128) + lane) = o;
    } else {  // D == 64
        const float2* hp = (const float2*)(hin + (size_t)warp * 64) + lane;
        float2 v = *hp;
        float2 acc = make_float2(di * v.x, di * v.y);
        int beg = rowptr[warp], end = rowptr[warp + 1];
        for (int e = beg; e < end; e++) {
            int s = colidx[e];
            float ds = __ldg(&dinv[s]);
            float2 u = *((const float2*)(hin + (size_t)s * 64) + lane);
            acc.x += ds * u.x; acc.y += ds * u.y;
        }
        float2 bb = *((const float2*)bias + lane);
        float2 o;
        o.x = di * acc.x + bb.x; o.y = di * acc.y + bb.y;
        if (RELU) { o.x = fmaxf(o.x, 0.f); o.y = fmaxf(o.y, 0.f); }
        *((float2*)(hout + (size_t)warp * 64) + lane) = o;
    }
}

// ---------------- global mean pool -------------------------------------------
__global__ void k_poolzero(float* out, int* gcnt) {
    int i = blockIdx.x * blockDim.x + threadIdx.x;
    if (i < GPOOL * DOUTP) out[i] = 0.f;
    if (i < GPOOL) gcnt[i] = 0;
}

__global__ void k_pool(const float* __restrict__ h, const int* __restrict__ batch,
                       float* out, int* gcnt, int n) {
    int idx = blockIdx.x * blockDim.x + threadIdx.x;
    int node = idx >> 6;
    int c = idx & 63;
    if (node >= n) return;
    int g = batch[node];
    atomicAdd(&out[g * DOUTP + c], h[(size_t)node * DOUTP + c]);
    if (c == 0) atomicAdd(&gcnt[g], 1);
}

__global__ void k_div(float* out, const int* __restrict__ gcnt) {
    int i = blockIdx.x * blockDim.x + threadIdx.x;
    if (i < GPOOL * DOUTP) {
        int c = gcnt[i >> 6];
        out[i] /= (float)(c > 0 ? c : 1);
    }
}

// ---------------- launch ------------------------------------------------------
extern "C" void kernel_launch(void* const* d_in, const int* in_sizes, int n_in,
                              void* d_out, int out_size) {
    const float* x     = (const float*)d_in[0];
    const int*   ei    = (const int*)d_in[1];
    const int*   batch = (const int*)d_in[2];
    const float* W1 = (const float*)d_in[3];
    const float* b1 = (const float*)d_in[4];
    const float* W2 = (const float*)d_in[5];
    const float* b2 = (const float*)d_in[6];
    const float* W3 = (const float*)d_in[7];
    const float* b3 = (const float*)d_in[8];
    float* out = (float*)d_out;

    int n = in_sizes[0] / 128;
    int E = in_sizes[1] / 2;

    float *h0, *h1, *dinv;
    int *cnt, *cur, *rowptr, *colidx, *bsum, *gcnt;
    cudaGetSymbolAddress((void**)&h0, g_h0);
    cudaGetSymbolAddress((void**)&h1, g_h1);
    cudaGetSymbolAddress((void**)&dinv, g_dinv);
    cudaGetSymbolAddress((void**)&cnt, g_cnt);
    cudaGetSymbolAddress((void**)&cur, g_cur);
    cudaGetSymbolAddress((void**)&rowptr, g_rowptr);
    cudaGetSymbolAddress((void**)&colidx, g_colidx);
    cudaGetSymbolAddress((void**)&bsum, g_bsum);
    cudaGetSymbolAddress((void**)&gcnt, g_gcnt);

    int nchunk = (n + CHUNK - 1) / CHUNK;

    // ---- CSR build ----
    k_zero<<<(n + 255) / 256, 256>>>(cnt, cur, n);
    k_count<<<(E + 255) / 256, 256>>>(ei, cnt, E);
    k_chunkscan<<<nchunk, CHUNK>>>(cnt, rowptr, bsum, dinv, n);
    k_bscan<<<1, MAXCHUNK>>>(bsum, nchunk, rowptr, n);
    k_addoff<<<(n + 255) / 256, 256>>>(rowptr, bsum, n);
    k_fill<<<(E + 255) / 256, 256>>>(ei, cur, rowptr, colidx, E);

    int gemm_grid = (n + 63) / 64;
    int agg_grid = (n + 7) / 8;  // 8 warps / block

    // ---- layer 1 ----
    k_gemm<128><<<gemm_grid, 256>>>(x, W1, h0, n);
    k_agg<128, true><<<agg_grid, 256>>>(h0, h1, dinv, rowptr, colidx, b1, n);
    // ---- layer 2 ----
    k_gemm<128><<<gemm_grid, 256>>>(h1, W2, h0, n);
    k_agg<128, true><<<agg_grid, 256>>>(h0, h1, dinv, rowptr, colidx, b2, n);
    // ---- layer 3 ----
    k_gemm<64><<<gemm_grid, 256>>>(h1, W3, h0, n);
    k_agg<64, false><<<agg_grid, 256>>>(h0, h1, dinv, rowptr, colidx, b3, n);

    // ---- global mean pool ----
    k_poolzero<<<(GPOOL * DOUTP + 255) / 256, 256>>>(out, gcnt);
    k_pool<<<((size_t)n * 64 + 255) / 256, 256>>>(h1, batch, out, gcnt, n);
    k_div<<<(GPOOL * DOUTP + 255) / 256, 256>>>(out, gcnt);
}

// round 3
// speedup vs baseline: 1.3004x; 1.3004x over previous
#include <cuda_runtime.h>
#include <cstdint>

#define NMAX 50048
#define EMAX 800000
#define GPOOL 512
#define DOUTP 64
#define CHUNK 512
#define MAXCHUNK 128   // supports up to 65536 nodes

// ---------------- scratch (device globals; no allocation allowed) -------------
__device__ float g_h0[(size_t)NMAX * 128];
__device__ float g_h1[(size_t)NMAX * 128];
__device__ float g_dinv[NMAX];
__device__ int   g_cnt[NMAX];
__device__ int   g_cur[NMAX];
__device__ int   g_rowptr[NMAX + 1];
__device__ int   g_colidx[EMAX];
__device__ int   g_bsum[MAXCHUNK];
__device__ int   g_gcnt[GPOOL];

// ---------------- CSR build -------------------------------------------------
__global__ void k_zero(int* cnt, int* cur, int n) {
    int i = blockIdx.x * blockDim.x + threadIdx.x;
    if (i < n) { cnt[i] = 0; cur[i] = 0; }
}

__global__ void k_count(const int* __restrict__ ei, int* cnt, int E) {
    int e = blockIdx.x * blockDim.x + threadIdx.x;
    if (e < E) {
        int d = ei[E + e];
        atomicAdd(&cnt[d], 1);
    }
}

__global__ void k_chunkscan(const int* __restrict__ cnt, int* rowptr, int* bsum,
                            float* dinv, int n) {
    __shared__ int sh[CHUNK];
    int tid = threadIdx.x;
    int i = blockIdx.x * CHUNK + tid;
    int v = (i < n) ? cnt[i] : 0;
    if (i < n) dinv[i] = rsqrtf((float)(v + 1));   // +1 for self loop
    sh[tid] = v;
    __syncthreads();
    for (int off = 1; off < CHUNK; off <<= 1) {
        int t = (tid >= off) ? sh[tid - off] : 0;
        __syncthreads();
        sh[tid] += t;
        __syncthreads();
    }
    if (i < n) rowptr[i] = sh[tid] - v;            // local exclusive
    if (tid == CHUNK - 1) bsum[blockIdx.x] = sh[tid];
}

__global__ void k_bscan(int* bsum, int nb, int* rowptr, int n) {
    __shared__ int sh[MAXCHUNK];
    int tid = threadIdx.x;
    int v = (tid < nb) ? bsum[tid] : 0;
    sh[tid] = v;
    __syncthreads();
    for (int off = 1; off < MAXCHUNK; off <<= 1) {
        int t = (tid >= off) ? sh[tid - off] : 0;
        __syncthreads();
        sh[tid] += t;
        __syncthreads();
    }
    if (tid < nb) bsum[tid] = sh[tid] - v;         // exclusive
    if (tid == MAXCHUNK - 1) rowptr[n] = sh[tid];
}

__global__ void k_addoff(int* rowptr, const int* __restrict__ bsum, int n) {
    int i = blockIdx.x * blockDim.x + threadIdx.x;
    if (i < n) rowptr[i] += bsum[i / CHUNK];
}

__global__ void k_fill(const int* __restrict__ ei, int* cur,
                       const int* __restrict__ rowptr, int* colidx, int E) {
    int e = blockIdx.x * blockDim.x + threadIdx.x;
    if (e < E) {
        int s = ei[e];
        int d = ei[E + e];
        int pos = atomicAdd(&cur[d], 1);
        colidx[rowptr[d] + pos] = s;
    }
}

// ---------------- tf32 helpers ------------------------------------------------
__device__ __forceinline__ void tf32split(float x, float& hi, float& lo) {
    float h; asm("cvt.rna.tf32.f32 %0, %1;" : "=f"(h) : "f"(x));
    float l = x - h;
    float lt; asm("cvt.rna.tf32.f32 %0, %1;" : "=f"(lt) : "f"(l));
    hi = h; lo = lt;
}

__device__ __forceinline__ void mma_tf32(float* d, const unsigned* a, unsigned b0, unsigned b1) {
    asm volatile(
        "mma.sync.aligned.m16n8k8.row.col.f32.tf32.tf32.f32 "
        "{%0,%1,%2,%3}, {%4,%5,%6,%7}, {%8,%9}, {%0,%1,%2,%3};\n"
        : "+f"(d[0]), "+f"(d[1]), "+f"(d[2]), "+f"(d[3])
        : "r"(a[0]), "r"(a[1]), "r"(a[2]), "r"(a[3]), "r"(b0), "r"(b1));
}

// ---------------- tensor-core GEMM: C[n x BN] = A[n x 128] @ B[128 x BN] -----
// 3xTF32 compensation (Ah*Bh + Ah*Bl + Al*Bh) -> ~fp32 accuracy.
// CTA: 256 threads (8 warps). BM=128, BK=16, warp = 16-row strip x BN cols.
template <int BN>
__global__ __launch_bounds__(256) void k_mma(const float* __restrict__ A,
                                             const float* __restrict__ B,
                                             float* __restrict__ C, int n) {
    constexpr int K = 128, BM = 128, BK = 16;
    constexpr int SA = BK + 4;        // 20 floats: conflict-free (20r+c distinct mod 32)
    constexpr int SB = BN + 8;        // stride ≡ 8 mod 32: (l&3)*8 + (l>>2) distinct
    constexpr int NT = BN / 8;        // n-tiles per warp

    __shared__ float sAh[BM * SA], sAl[BM * SA];
    __shared__ float sBh[BK * SB], sBl[BK * SB];

    int tid = threadIdx.x;
    int lane = tid & 31, warp = tid >> 5;
    int bm = blockIdx.x * BM;
    int r = lane >> 2, c = lane & 3;

    float acc[NT][4];
#pragma unroll
    for (int t = 0; t < NT; t++)
#pragma unroll
        for (int j = 0; j < 4; j++) acc[t][j] = 0.f;

    const float4 zero4 = make_float4(0.f, 0.f, 0.f, 0.f);

    for (int ch = 0; ch < K / BK; ch++) {
        int k0 = ch * BK;
        // ---- load A chunk [BM x BK] ----
#pragma unroll
        for (int j = 0; j < (BM * BK / 4) / 256; j++) {
            int idx = tid + 256 * j;
            int row = idx >> 2, c4 = idx & 3;      // 4 float4 per row
            int gm = bm + row;
            float4 av = (gm < n) ? *(const float4*)(A + (size_t)gm * K + k0 + c4 * 4) : zero4;
            float4 h4, l4;
            tf32split(av.x, h4.x, l4.x); tf32split(av.y, h4.y, l4.y);
            tf32split(av.z, h4.z, l4.z); tf32split(av.w, h4.w, l4.w);
            *(float4*)&sAh[row * SA + c4 * 4] = h4;
            *(float4*)&sAl[row * SA + c4 * 4] = l4;
        }
        // ---- load B chunk [BK x BN] ----
#pragma unroll
        for (int j = 0; j < (BK * BN / 4) / 256 + ((BK * BN / 4) % 256 != 0); j++) {
            int idx = tid + 256 * j;
            if (idx < BK * BN / 4) {
                int row = idx / (BN / 4), c4 = idx % (BN / 4);
                float4 bv = *(const float4*)(B + (size_t)(k0 + row) * BN + c4 * 4);
                float4 h4, l4;
                tf32split(bv.x, h4.x, l4.x); tf32split(bv.y, h4.y, l4.y);
                tf32split(bv.z, h4.z, l4.z); tf32split(bv.w, h4.w, l4.w);
                *(float4*)&sBh[row * SB + c4 * 4] = h4;
                *(float4*)&sBl[row * SB + c4 * 4] = l4;
            }
        }
        __syncthreads();

#pragma unroll
        for (int kk = 0; kk < BK / 8; kk++) {
            int ab = (warp * 16 + r) * SA + kk * 8 + c;
            unsigned ah[4], al[4];
            ah[0] = __float_as_uint(sAh[ab]);
            ah[1] = __float_as_uint(sAh[ab + 8 * SA]);
            ah[2] = __float_as_uint(sAh[ab + 4]);
            ah[3] = __float_as_uint(sAh[ab + 8 * SA + 4]);
            al[0] = __float_as_uint(sAl[ab]);
            al[1] = __float_as_uint(sAl[ab + 8 * SA]);
            al[2] = __float_as_uint(sAl[ab + 4]);
            al[3] = __float_as_uint(sAl[ab + 8 * SA + 4]);
#pragma unroll
            for (int nt = 0; nt < NT; nt++) {
                int bb = (kk * 8 + c) * SB + nt * 8 + r;
                unsigned bh0 = __float_as_uint(sBh[bb]);
                unsigned bh1 = __float_as_uint(sBh[bb + 4 * SB]);
                unsigned bl0 = __float_as_uint(sBl[bb]);
                unsigned bl1 = __float_as_uint(sBl[bb + 4 * SB]);
                mma_tf32(acc[nt], al, bh0, bh1);
                mma_tf32(acc[nt], ah, bl0, bl1);
                mma_tf32(acc[nt], ah, bh0, bh1);
            }
        }
        __syncthreads();
    }

    // ---- epilogue ----
    int m0 = bm + warp * 16 + r;
    int m1 = m0 + 8;
#pragma unroll
    for (int nt = 0; nt < NT; nt++) {
        int cc = nt * 8 + c * 2;
        if (m0 < n) *(float2*)(C + (size_t)m0 * BN + cc) = make_float2(acc[nt][0], acc[nt][1]);
        if (m1 < n) *(float2*)(C + (size_t)m1 * BN + cc) = make_float2(acc[nt][2], acc[nt][3]);
    }
}

// ---------------- fused normalized aggregation + bias (+relu) ----------------
// out[d] = relu( dinv[d]*( sum_s dinv[s]*h[s] + dinv[d]*h[d] ) + bias )
template <int D, bool RELU>
__global__ void k_agg(const float* __restrict__ hin, float* __restrict__ hout,
                      const float* __restrict__ dinv, const int* __restrict__ rowptr,
                      const int* __restrict__ colidx, const float* __restrict__ bias,
                      int n) {
    int warp = (blockIdx.x * blockDim.x + threadIdx.x) >> 5;
    int lane = threadIdx.x & 31;
    if (warp >= n) return;
    float di = dinv[warp];

    if constexpr (D == 128) {
        const float4* hp = (const float4*)(hin + (size_t)warp * 128) + lane;
        float4 v = *hp;
        float4 acc = make_float4(di * v.x, di * v.y, di * v.z, di * v.w);
        int beg = rowptr[warp], end = rowptr[warp + 1];
        for (int e = beg; e < end; e++) {
            int s = colidx[e];
            float ds = __ldg(&dinv[s]);
            float4 u = *((const float4*)(hin + (size_t)s * 128) + lane);
            acc.x += ds * u.x; acc.y += ds * u.y;
            acc.z += ds * u.z; acc.w += ds * u.w;
        }
        float4 bb = *((const float4*)bias + lane);
        float4 o;
        o.x = di * acc.x + bb.x; o.y = di * acc.y + bb.y;
        o.z = di * acc.z + bb.z; o.w = di * acc.w + bb.w;
        if (RELU) {
            o.x = fmaxf(o.x, 0.f); o.y = fmaxf(o.y, 0.f);
            o.z = fmaxf(o.z, 0.f); o.w = fmaxf(o.w, 0.f);
        }
        *((float4*)(hout + (size_t)warp * 128) + lane) = o;
    } else {  // D == 64
        const float2* hp = (const float2*)(hin + (size_t)warp * 64) + lane;
        float2 v = *hp;
        float2 acc = make_float2(di * v.x, di * v.y);
        int beg = rowptr[warp], end = rowptr[warp + 1];
        for (int e = beg; e < end; e++) {
            int s = colidx[e];
            float ds = __ldg(&dinv[s]);
            float2 u = *((const float2*)(hin + (size_t)s * 64) + lane);
            acc.x += ds * u.x; acc.y += ds * u.y;
        }
        float2 bb = *((const float2*)bias + lane);
        float2 o;
        o.x = di * acc.x + bb.x; o.y = di * acc.y + bb.y;
        if (RELU) { o.x = fmaxf(o.x, 0.f); o.y = fmaxf(o.y, 0.f); }
        *((float2*)(hout + (size_t)warp * 64) + lane) = o;
    }
}

// ---------------- global mean pool -------------------------------------------
__global__ void k_poolzero(float* out, int* gcnt) {
    int i = blockIdx.x * blockDim.x + threadIdx.x;
    if (i < GPOOL * DOUTP) out[i] = 0.f;
    if (i < GPOOL) gcnt[i] = 0;
}

__global__ void k_pool(const float* __restrict__ h, const int* __restrict__ batch,
                       float* out, int* gcnt, int n) {
    int idx = blockIdx.x * blockDim.x + threadIdx.x;
    int node = idx >> 6;
    int c = idx & 63;
    if (node >= n) return;
    int g = batch[node];
    atomicAdd(&out[g * DOUTP + c], h[(size_t)node * DOUTP + c]);
    if (c == 0) atomicAdd(&gcnt[g], 1);
}

__global__ void k_div(float* out, const int* __restrict__ gcnt) {
    int i = blockIdx.x * blockDim.x + threadIdx.x;
    if (i < GPOOL * DOUTP) {
        int c = gcnt[i >> 6];
        out[i] /= (float)(c > 0 ? c : 1);
    }
}

// ---------------- launch ------------------------------------------------------
extern "C" void kernel_launch(void* const* d_in, const int* in_sizes, int n_in,
                              void* d_out, int out_size) {
    const float* x     = (const float*)d_in[0];
    const int*   ei    = (const int*)d_in[1];
    const int*   batch = (const int*)d_in[2];
    const float* W1 = (const float*)d_in[3];
    const float* b1 = (const float*)d_in[4];
    const float* W2 = (const float*)d_in[5];
    const float* b2 = (const float*)d_in[6];
    const float* W3 = (const float*)d_in[7];
    const float* b3 = (const float*)d_in[8];
    float* out = (float*)d_out;

    int n = in_sizes[0] / 128;
    int E = in_sizes[1] / 2;

    float *h0, *h1, *dinv;
    int *cnt, *cur, *rowptr, *colidx, *bsum, *gcnt;
    cudaGetSymbolAddress((void**)&h0, g_h0);
    cudaGetSymbolAddress((void**)&h1, g_h1);
    cudaGetSymbolAddress((void**)&dinv, g_dinv);
    cudaGetSymbolAddress((void**)&cnt, g_cnt);
    cudaGetSymbolAddress((void**)&cur, g_cur);
    cudaGetSymbolAddress((void**)&rowptr, g_rowptr);
    cudaGetSymbolAddress((void**)&colidx, g_colidx);
    cudaGetSymbolAddress((void**)&bsum, g_bsum);
    cudaGetSymbolAddress((void**)&gcnt, g_gcnt);

    int nchunk = (n + CHUNK - 1) / CHUNK;
    int mma_grid = (n + 127) / 128;
    int agg_grid = (n + 7) / 8;  // 8 warps / block

    // ---- CSR build (layer-1 GEMM interleaved; independent of CSR) ----
    k_zero<<<(n + 255) / 256, 256>>>(cnt, cur, n);
    k_count<<<(E + 255) / 256, 256>>>(ei, cnt, E);
    k_chunkscan<<<nchunk, CHUNK>>>(cnt, rowptr, bsum, dinv, n);
    k_mma<128><<<mma_grid, 256>>>(x, W1, h0, n);          // layer-1 transform
    k_bscan<<<1, MAXCHUNK>>>(bsum, nchunk, rowptr, n);
    k_addoff<<<(n + 255) / 256, 256>>>(rowptr, bsum, n);
    k_fill<<<(E + 255) / 256, 256>>>(ei, cur, rowptr, colidx, E);

    // ---- layer 1 agg ----
    k_agg<128, true><<<agg_grid, 256>>>(h0, h1, dinv, rowptr, colidx, b1, n);
    // ---- layer 2 ----
    k_mma<128><<<mma_grid, 256>>>(h1, W2, h0, n);
    k_agg<128, true><<<agg_grid, 256>>>(h0, h1, dinv, rowptr, colidx, b2, n);
    // ---- layer 3 ----
    k_mma<64><<<mma_grid, 256>>>(h1, W3, h0, n);
    k_agg<64, false><<<agg_grid, 256>>>(h0, h1, dinv, rowptr, colidx, b3, n);

    // ---- global mean pool ----
    k_poolzero<<<(GPOOL * DOUTP + 255) / 256, 256>>>(out, gcnt);
    k_pool<<<((size_t)n * 64 + 255) / 256, 256>>>(h1, batch, out, gcnt, n);
    k_div<<<(GPOOL * DOUTP + 255) / 256, 256>>>(out, gcnt);
}

// round 4
// speedup vs baseline: 1.5590x; 1.1989x over previous
#include <cuda_runtime.h>
#include <cuda_bf16.h>
#include <cstdint>

#define NMAX 50048
#define EMAX 800000
#define GPOOL 512
#define DOUTP 64
#define CHUNK 512
#define MAXCHUNK 128   // supports up to 65536 nodes

// ---------------- scratch (device globals; no allocation allowed) -------------
__device__ float g_h0[(size_t)NMAX * 128];
__device__ float g_h1[(size_t)NMAX * 128];
__device__ float g_dinv[NMAX];
__device__ int   g_cnt[NMAX];
__device__ int   g_cur[NMAX];
__device__ int   g_rowptr[NMAX + 1];
__device__ int   g_colidx[EMAX];
__device__ int   g_bsum[MAXCHUNK];
__device__ int   g_gcnt[GPOOL];

// ---------------- CSR build -------------------------------------------------
__global__ void k_zero(int* cnt, int* cur, int n) {
    int i = blockIdx.x * blockDim.x + threadIdx.x;
    if (i < n) { cnt[i] = 0; cur[i] = 0; }
}

__global__ void k_count(const int* __restrict__ ei, int* cnt, int E) {
    int e = blockIdx.x * blockDim.x + threadIdx.x;
    if (e < E) {
        int d = ei[E + e];
        atomicAdd(&cnt[d], 1);
    }
}

__global__ void k_chunkscan(const int* __restrict__ cnt, int* rowptr, int* bsum,
                            float* dinv, int n) {
    __shared__ int sh[CHUNK];
    int tid = threadIdx.x;
    int i = blockIdx.x * CHUNK + tid;
    int v = (i < n) ? cnt[i] : 0;
    if (i < n) dinv[i] = rsqrtf((float)(v + 1));   // +1 for self loop
    sh[tid] = v;
    __syncthreads();
    for (int off = 1; off < CHUNK; off <<= 1) {
        int t = (tid >= off) ? sh[tid - off] : 0;
        __syncthreads();
        sh[tid] += t;
        __syncthreads();
    }
    if (i < n) rowptr[i] = sh[tid] - v;            // local exclusive
    if (tid == CHUNK - 1) bsum[blockIdx.x] = sh[tid];
}

__global__ void k_bscan(int* bsum, int nb, int* rowptr, int n) {
    __shared__ int sh[MAXCHUNK];
    int tid = threadIdx.x;
    int v = (tid < nb) ? bsum[tid] : 0;
    sh[tid] = v;
    __syncthreads();
    for (int off = 1; off < MAXCHUNK; off <<= 1) {
        int t = (tid >= off) ? sh[tid - off] : 0;
        __syncthreads();
        sh[tid] += t;
        __syncthreads();
    }
    if (tid < nb) bsum[tid] = sh[tid] - v;         // exclusive
    if (tid == MAXCHUNK - 1) rowptr[n] = sh[tid];
}

__global__ void k_addoff(int* rowptr, const int* __restrict__ bsum, int n) {
    int i = blockIdx.x * blockDim.x + threadIdx.x;
    if (i < n) rowptr[i] += bsum[i / CHUNK];
}

__global__ void k_fill(const int* __restrict__ ei, int* cur,
                       const int* __restrict__ rowptr, int* colidx, int E) {
    int e = blockIdx.x * blockDim.x + threadIdx.x;
    if (e < E) {
        int s = ei[e];
        int d = ei[E + e];
        int pos = atomicAdd(&cur[d], 1);
        colidx[rowptr[d] + pos] = s;
    }
}

// ---------------- bf16 helpers ------------------------------------------------
__device__ __forceinline__ void bf16split(float x, unsigned short& hi, unsigned short& lo) {
    __nv_bfloat16 h = __float2bfloat16(x);
    float r = x - __bfloat162float(h);
    __nv_bfloat16 l = __float2bfloat16(r);
    hi = *(unsigned short*)&h;
    lo = *(unsigned short*)&l;
}

__device__ __forceinline__ void mma_bf16(float* d, const unsigned* a, unsigned b0, unsigned b1) {
    asm volatile(
        "mma.sync.aligned.m16n8k16.row.col.f32.bf16.bf16.f32 "
        "{%0,%1,%2,%3}, {%4,%5,%6,%7}, {%8,%9}, {%0,%1,%2,%3};\n"
        : "+f"(d[0]), "+f"(d[1]), "+f"(d[2]), "+f"(d[3])
        : "r"(a[0]), "r"(a[1]), "r"(a[2]), "r"(a[3]), "r"(b0), "r"(b1));
}

__device__ __forceinline__ void ldsm_x4(unsigned* r, unsigned addr) {
    asm volatile("ldmatrix.sync.aligned.m8n8.x4.shared.b16 {%0,%1,%2,%3}, [%4];"
                 : "=r"(r[0]), "=r"(r[1]), "=r"(r[2]), "=r"(r[3]) : "r"(addr));
}

__device__ __forceinline__ void ldsm_x4_t(unsigned* r, unsigned addr) {
    asm volatile("ldmatrix.sync.aligned.m8n8.x4.trans.shared.b16 {%0,%1,%2,%3}, [%4];"
                 : "=r"(r[0]), "=r"(r[1]), "=r"(r[2]), "=r"(r[3]) : "r"(addr));
}

// ---------------- tensor-core GEMM: C[n x BN] = A[n x 128] @ B[128 x BN] -----
// 3xBF16 compensation (Al*Bh + Ah*Bl + Ah*Bh) -> ~fp32 accuracy.
// CTA: 256 threads (8 warps, 4 in M x 2 in N). BM=128, BK=16.
// Warp tile: 32 rows (2 x m16) x BN/2 cols.
template <int BN>
__global__ __launch_bounds__(256, 2) void k_mma(const float* __restrict__ A,
                                                const float* __restrict__ B,
                                                float* __restrict__ C, int n) {
    constexpr int K = 128, BM = 128, BK = 16;
    constexpr int SA = 24;            // A row stride (bf16): 48B -> ldsm conflict-free
    constexpr int SB = BN + 8;        // B row stride (bf16)
    constexpr int WN = BN / 2;        // warp n-extent
    constexpr int NP = WN / 16;       // n-tile pairs per warp
    constexpr int NT = WN / 8;        // n8 tiles per warp

    __shared__ unsigned short sAh[BM * SA], sAl[BM * SA];
    __shared__ unsigned short sBh[BK * SB], sBl[BK * SB];

    int tid = threadIdx.x;
    int lane = tid & 31, warp = tid >> 5;
    int wm = warp >> 1, wn = warp & 1;
    int bm = blockIdx.x * BM;

    float acc[2][NT][4];
#pragma unroll
    for (int mt = 0; mt < 2; mt++)
#pragma unroll
        for (int t = 0; t < NT; t++)
#pragma unroll
            for (int j = 0; j < 4; j++) acc[mt][t][j] = 0.f;

    const float4 zero4 = make_float4(0.f, 0.f, 0.f, 0.f);

    // precompute ldmatrix smem addresses (lane-dependent, chunk-invariant)
    unsigned aBaseH = (unsigned)__cvta_generic_to_shared(sAh);
    unsigned aBaseL = (unsigned)__cvta_generic_to_shared(sAl);
    unsigned bBaseH = (unsigned)__cvta_generic_to_shared(sBh);
    unsigned bBaseL = (unsigned)__cvta_generic_to_shared(sBl);
    int aRow = wm * 32 + (lane & 15);
    unsigned aOff = (unsigned)((aRow * SA + (lane >> 4) * 8) * 2);
    int bRow = lane & 15;
    unsigned bOff = (unsigned)((bRow * SB + wn * WN + (lane >> 4) * 8) * 2);

    for (int ch = 0; ch < K / BK; ch++) {
        int k0 = ch * BK;
        // ---- load + split A chunk [BM x BK] : 512 float4 tasks / 256 thr ----
#pragma unroll
        for (int j = 0; j < 2; j++) {
            int idx = tid + 256 * j;
            int row = idx >> 2, q = idx & 3;
            int gm = bm + row;
            float4 av = (gm < n) ? *(const float4*)(A + (size_t)gm * K + k0 + q * 4) : zero4;
            unsigned short h0, l0, h1, l1, h2, l2, h3, l3;
            bf16split(av.x, h0, l0); bf16split(av.y, h1, l1);
            bf16split(av.z, h2, l2); bf16split(av.w, h3, l3);
            int o = row * SA + q * 4;
            sAh[o] = h0; sAh[o + 1] = h1; sAh[o + 2] = h2; sAh[o + 3] = h3;
            sAl[o] = l0; sAl[o + 1] = l1; sAl[o + 2] = l2; sAl[o + 3] = l3;
        }
        // ---- load + split B chunk [BK x BN] ----
#pragma unroll
        for (int j = 0; j < (BK * BN / 4 + 255) / 256; j++) {
            int idx = tid + 256 * j;
            if (idx < BK * BN / 4) {
                int row = idx / (BN / 4), q = idx % (BN / 4);
                float4 bv = *(const float4*)(B + (size_t)(k0 + row) * BN + q * 4);
                unsigned short h0, l0, h1, l1, h2, l2, h3, l3;
                bf16split(bv.x, h0, l0); bf16split(bv.y, h1, l1);
                bf16split(bv.z, h2, l2); bf16split(bv.w, h3, l3);
                int o = row * SB + q * 4;
                sBh[o] = h0; sBh[o + 1] = h1; sBh[o + 2] = h2; sBh[o + 3] = h3;
                sBl[o] = l0; sBl[o + 1] = l1; sBl[o + 2] = l2; sBl[o + 3] = l3;
            }
        }
        __syncthreads();

        // ---- A fragments for both m16 tiles ----
        unsigned ah[2][4], al[2][4];
#pragma unroll
        for (int mt = 0; mt < 2; mt++) {
            unsigned off = aOff + (unsigned)(mt * 16 * SA * 2);
            ldsm_x4(ah[mt], aBaseH + off);
            ldsm_x4(al[mt], aBaseL + off);
        }

        // ---- loop over n-tile pairs ----
#pragma unroll
        for (int np = 0; np < NP; np++) {
            unsigned off = bOff + (unsigned)(np * 16 * 2);
            unsigned bh[4], bl[4];
            ldsm_x4_t(bh, bBaseH + off);   // regs {0,1}: n8 tile 2*np; {2,3}: 2*np+1
            ldsm_x4_t(bl, bBaseL + off);
#pragma unroll
            for (int mt = 0; mt < 2; mt++) {
#pragma unroll
                for (int sub = 0; sub < 2; sub++) {
                    float* d = acc[mt][np * 2 + sub];
                    mma_bf16(d, al[mt], bh[sub * 2], bh[sub * 2 + 1]);
                    mma_bf16(d, ah[mt], bl[sub * 2], bl[sub * 2 + 1]);
                    mma_bf16(d, ah[mt], bh[sub * 2], bh[sub * 2 + 1]);
                }
            }
        }
        __syncthreads();
    }

    // ---- epilogue ----
    int r = lane >> 2, c2 = (lane & 3) * 2;
#pragma unroll
    for (int mt = 0; mt < 2; mt++) {
        int m0 = bm + wm * 32 + mt * 16 + r;
        int m1 = m0 + 8;
#pragma unroll
        for (int nt = 0; nt < NT; nt++) {
            int cc = wn * WN + nt * 8 + c2;
            if (m0 < n) *(float2*)(C + (size_t)m0 * BN + cc) = make_float2(acc[mt][nt][0], acc[mt][nt][1]);
            if (m1 < n) *(float2*)(C + (size_t)m1 * BN + cc) = make_float2(acc[mt][nt][2], acc[mt][nt][3]);
        }
    }
}

// ---------------- fused normalized aggregation + bias (+relu) ----------------
// out[d] = relu( dinv[d]*( sum_s dinv[s]*h[s] + dinv[d]*h[d] ) + bias )
template <int D, bool RELU>
__global__ void k_agg(const float* __restrict__ hin, float* __restrict__ hout,
                      const float* __restrict__ dinv, const int* __restrict__ rowptr,
                      const int* __restrict__ colidx, const float* __restrict__ bias,
                      int n) {
    int warp = (blockIdx.x * blockDim.x + threadIdx.x) >> 5;
    int lane = threadIdx.x & 31;
    if (warp >= n) return;
    float di = dinv[warp];

    if constexpr (D == 128) {
        const float4* hp = (const float4*)(hin + (size_t)warp * 128) + lane;
        float4 v = *hp;
        float4 acc = make_float4(di * v.x, di * v.y, di * v.z, di * v.w);
        int beg = rowptr[warp], end = rowptr[warp + 1];
        for (int e = beg; e < end; e++) {
            int s = colidx[e];
            float ds = __ldg(&dinv[s]);
            float4 u = *((const float4*)(hin + (size_t)s * 128) + lane);
            acc.x += ds * u.x; acc.y += ds * u.y;
            acc.z += ds * u.z; acc.w += ds * u.w;
        }
        float4 bb = *((const float4*)bias + lane);
        float4 o;
        o.x = di * acc.x + bb.x; o.y = di * acc.y + bb.y;
        o.z = di * acc.z + bb.z; o.w = di * acc.w + bb.w;
        if (RELU) {
            o.x = fmaxf(o.x, 0.f); o.y = fmaxf(o.y, 0.f);
            o.z = fmaxf(o.z, 0.f); o.w = fmaxf(o.w, 0.f);
        }
        *((float4*)(hout + (size_t)warp * 128) + lane) = o;
    } else {  // D == 64
        const float2* hp = (const float2*)(hin + (size_t)warp * 64) + lane;
        float2 v = *hp;
        float2 acc = make_float2(di * v.x, di * v.y);
        int beg = rowptr[warp], end = rowptr[warp + 1];
        for (int e = beg; e < end; e++) {
            int s = colidx[e];
            float ds = __ldg(&dinv[s]);
            float2 u = *((const float2*)(hin + (size_t)s * 64) + lane);
            acc.x += ds * u.x; acc.y += ds * u.y;
        }
        float2 bb = *((const float2*)bias + lane);
        float2 o;
        o.x = di * acc.x + bb.x; o.y = di * acc.y + bb.y;
        if (RELU) { o.x = fmaxf(o.x, 0.f); o.y = fmaxf(o.y, 0.f); }
        *((float2*)(hout + (size_t)warp * 64) + lane) = o;
    }
}

// ---------------- global mean pool -------------------------------------------
__global__ void k_poolzero(float* out, int* gcnt) {
    int i = blockIdx.x * blockDim.x + threadIdx.x;
    if (i < GPOOL * DOUTP) out[i] = 0.f;
    if (i < GPOOL) gcnt[i] = 0;
}

__global__ void k_pool(const float* __restrict__ h, const int* __restrict__ batch,
                       float* out, int* gcnt, int n) {
    int idx = blockIdx.x * blockDim.x + threadIdx.x;
    int node = idx >> 6;
    int c = idx & 63;
    if (node >= n) return;
    int g = batch[node];
    atomicAdd(&out[g * DOUTP + c], h[(size_t)node * DOUTP + c]);
    if (c == 0) atomicAdd(&gcnt[g], 1);
}

__global__ void k_div(float* out, const int* __restrict__ gcnt) {
    int i = blockIdx.x * blockDim.x + threadIdx.x;
    if (i < GPOOL * DOUTP) {
        int c = gcnt[i >> 6];
        out[i] /= (float)(c > 0 ? c : 1);
    }
}

// ---------------- launch ------------------------------------------------------
extern "C" void kernel_launch(void* const* d_in, const int* in_sizes, int n_in,
                              void* d_out, int out_size) {
    const float* x     = (const float*)d_in[0];
    const int*   ei    = (const int*)d_in[1];
    const int*   batch = (const int*)d_in[2];
    const float* W1 = (const float*)d_in[3];
    const float* b1 = (const float*)d_in[4];
    const float* W2 = (const float*)d_in[5];
    const float* b2 = (const float*)d_in[6];
    const float* W3 = (const float*)d_in[7];
    const float* b3 = (const float*)d_in[8];
    float* out = (float*)d_out;

    int n = in_sizes[0] / 128;
    int E = in_sizes[1] / 2;

    float *h0, *h1, *dinv;
    int *cnt, *cur, *rowptr, *colidx, *bsum, *gcnt;
    cudaGetSymbolAddress((void**)&h0, g_h0);
    cudaGetSymbolAddress((void**)&h1, g_h1);
    cudaGetSymbolAddress((void**)&dinv, g_dinv);
    cudaGetSymbolAddress((void**)&cnt, g_cnt);
    cudaGetSymbolAddress((void**)&cur, g_cur);
    cudaGetSymbolAddress((void**)&rowptr, g_rowptr);
    cudaGetSymbolAddress((void**)&colidx, g_colidx);
    cudaGetSymbolAddress((void**)&bsum, g_bsum);
    cudaGetSymbolAddress((void**)&gcnt, g_gcnt);

    int nchunk = (n + CHUNK - 1) / CHUNK;
    int mma_grid = (n + 127) / 128;
    int agg_grid = (n + 7) / 8;  // 8 warps / block

    // ---- CSR build (layer-1 GEMM interleaved; independent of CSR) ----
    k_zero<<<(n + 255) / 256, 256>>>(cnt, cur, n);
    k_count<<<(E + 255) / 256, 256>>>(ei, cnt, E);
    k_chunkscan<<<nchunk, CHUNK>>>(cnt, rowptr, bsum, dinv, n);
    k_mma<128><<<mma_grid, 256>>>(x, W1, h0, n);          // layer-1 transform
    k_bscan<<<1, MAXCHUNK>>>(bsum, nchunk, rowptr, n);
    k_addoff<<<(n + 255) / 256, 256>>>(rowptr, bsum, n);
    k_fill<<<(E + 255) / 256, 256>>>(ei, cur, rowptr, colidx, E);

    // ---- layer 1 agg ----
    k_agg<128, true><<<agg_grid, 256>>>(h0, h1, dinv, rowptr, colidx, b1, n);
    // ---- layer 2 ----
    k_mma<128><<<mma_grid, 256>>>(h1, W2, h0, n);
    k_agg<128, true><<<agg_grid, 256>>>(h0, h1, dinv, rowptr, colidx, b2, n);
    // ---- layer 3 ----
    k_mma<64><<<mma_grid, 256>>>(h1, W3, h0, n);
    k_agg<64, false><<<agg_grid, 256>>>(h0, h1, dinv, rowptr, colidx, b3, n);

    // ---- global mean pool ----
    k_poolzero<<<(GPOOL * DOUTP + 255) / 256, 256>>>(out, gcnt);
    k_pool<<<((size_t)n * 64 + 255) / 256, 256>>>(h1, batch, out, gcnt, n);
    k_div<<<(GPOOL * DOUTP + 255) / 256, 256>>>(out, gcnt);
}

// round 5
// speedup vs baseline: 1.6496x; 1.0581x over previous
#include <cuda_runtime.h>
#include <cuda_bf16.h>
#include <cstdint>

#define NMAX 50048
#define EMAX 800000
#define GPOOL 512
#define DOUTP 64
#define CHUNK 512
#define MAXCHUNK 128   // supports up to 65536 nodes

// ---------------- scratch (device globals; no allocation allowed) -------------
__device__ float g_h0[(size_t)NMAX * 128];
__device__ float g_h1[(size_t)NMAX * 128];
__device__ float g_dinv[NMAX];
__device__ int   g_cnt[NMAX];
__device__ int   g_cur[NMAX];
__device__ int   g_rowptr[NMAX + 1];
__device__ int   g_colidx[EMAX];
__device__ int   g_bsum[MAXCHUNK];
__device__ int   g_gcnt[GPOOL];

// ---------------- CSR build -------------------------------------------------
__global__ void k_zero(int* cnt, int* cur, int n) {
    int i = blockIdx.x * blockDim.x + threadIdx.x;
    if (i < n) { cnt[i] = 0; cur[i] = 0; }
}

__global__ void k_count(const int* __restrict__ ei, int* cnt, int E) {
    int e = blockIdx.x * blockDim.x + threadIdx.x;
    if (e < E) {
        int d = ei[E + e];
        atomicAdd(&cnt[d], 1);
    }
}

__global__ void k_chunkscan(const int* __restrict__ cnt, int* rowptr, int* bsum,
                            float* dinv, int n) {
    __shared__ int sh[CHUNK];
    int tid = threadIdx.x;
    int i = blockIdx.x * CHUNK + tid;
    int v = (i < n) ? cnt[i] : 0;
    if (i < n) dinv[i] = rsqrtf((float)(v + 1));   // +1 for self loop
    sh[tid] = v;
    __syncthreads();
    for (int off = 1; off < CHUNK; off <<= 1) {
        int t = (tid >= off) ? sh[tid - off] : 0;
        __syncthreads();
        sh[tid] += t;
        __syncthreads();
    }
    if (i < n) rowptr[i] = sh[tid] - v;            // local exclusive
    if (tid == CHUNK - 1) bsum[blockIdx.x] = sh[tid];
}

__global__ void k_bscan(int* bsum, int nb, int* rowptr, int n) {
    __shared__ int sh[MAXCHUNK];
    int tid = threadIdx.x;
    int v = (tid < nb) ? bsum[tid] : 0;
    sh[tid] = v;
    __syncthreads();
    for (int off = 1; off < MAXCHUNK; off <<= 1) {
        int t = (tid >= off) ? sh[tid - off] : 0;
        __syncthreads();
        sh[tid] += t;
        __syncthreads();
    }
    if (tid < nb) bsum[tid] = sh[tid] - v;         // exclusive
    if (tid == MAXCHUNK - 1) rowptr[n] = sh[tid];
}

__global__ void k_addoff(int* rowptr, const int* __restrict__ bsum, int n) {
    int i = blockIdx.x * blockDim.x + threadIdx.x;
    if (i < n) rowptr[i] += bsum[i / CHUNK];
}

__global__ void k_fill(const int* __restrict__ ei, int* cur,
                       const int* __restrict__ rowptr, int* colidx, int E) {
    int e = blockIdx.x * blockDim.x + threadIdx.x;
    if (e < E) {
        int s = ei[e];
        int d = ei[E + e];
        int pos = atomicAdd(&cur[d], 1);
        colidx[rowptr[d] + pos] = s;
    }
}

// ---------------- bf16 helpers ------------------------------------------------
__device__ __forceinline__ void bf16split(float x, unsigned short& hi, unsigned short& lo) {
    __nv_bfloat16 h = __float2bfloat16(x);
    float r = x - __bfloat162float(h);
    __nv_bfloat16 l = __float2bfloat16(r);
    hi = *(unsigned short*)&h;
    lo = *(unsigned short*)&l;
}

__device__ __forceinline__ void mma_bf16(float* d, const unsigned* a, unsigned b0, unsigned b1) {
    asm volatile(
        "mma.sync.aligned.m16n8k16.row.col.f32.bf16.bf16.f32 "
        "{%0,%1,%2,%3}, {%4,%5,%6,%7}, {%8,%9}, {%0,%1,%2,%3};\n"
        : "+f"(d[0]), "+f"(d[1]), "+f"(d[2]), "+f"(d[3])
        : "r"(a[0]), "r"(a[1]), "r"(a[2]), "r"(a[3]), "r"(b0), "r"(b1));
}

__device__ __forceinline__ void ldsm_x4(unsigned* r, unsigned addr) {
    asm volatile("ldmatrix.sync.aligned.m8n8.x4.shared.b16 {%0,%1,%2,%3}, [%4];"
                 : "=r"(r[0]), "=r"(r[1]), "=r"(r[2]), "=r"(r[3]) : "r"(addr));
}

__device__ __forceinline__ void ldsm_x4_t(unsigned* r, unsigned addr) {
    asm volatile("ldmatrix.sync.aligned.m8n8.x4.trans.shared.b16 {%0,%1,%2,%3}, [%4];"
                 : "=r"(r[0]), "=r"(r[1]), "=r"(r[2]), "=r"(r[3]) : "r"(addr));
}

// ---------------- tensor-core GEMM: C[n x BN] = A[n x 128] @ B[128 x BN] -----
// 3xBF16 compensation (Al*Bh + Ah*Bl + Ah*Bh) -> ~fp32 accuracy.
// A staged via cp.async double-buffer; B prefetched in registers.
// CTA: 256 threads (8 warps, 4M x 2N). BM=128, BK=16. Warp: 32 x BN/2.
template <int BN>
__global__ __launch_bounds__(256, 2) void k_mma(const float* __restrict__ A,
                                                const float* __restrict__ B,
                                                float* __restrict__ C, int n) {
    constexpr int K = 128, BM = 128, BK = 16;
    constexpr int SA = 24;            // A row stride (bf16)
    constexpr int SB = BN + 8;        // B row stride (bf16)
    constexpr int WN = BN / 2;
    constexpr int NP = WN / 16;
    constexpr int NT = WN / 8;
    constexpr int BJ = (BK * BN / 4 + 255) / 256;   // B float4 loads / thread

    __shared__ float stA[2][BM * BK];               // fp32 staging (cp.async)
    __shared__ unsigned short sAh[BM * SA], sAl[BM * SA];
    __shared__ unsigned short sBh[BK * SB], sBl[BK * SB];

    int tid = threadIdx.x;
    int lane = tid & 31, warp = tid >> 5;
    int wm = warp >> 1, wn = warp & 1;
    int bm = blockIdx.x * BM;

    float acc[2][NT][4];
#pragma unroll
    for (int mt = 0; mt < 2; mt++)
#pragma unroll
        for (int t = 0; t < NT; t++)
#pragma unroll
            for (int j = 0; j < 4; j++) acc[mt][t][j] = 0.f;

    unsigned stBase0 = (unsigned)__cvta_generic_to_shared(stA[0]);
    unsigned stBase1 = (unsigned)__cvta_generic_to_shared(stA[1]);
    unsigned aBaseH = (unsigned)__cvta_generic_to_shared(sAh);
    unsigned aBaseL = (unsigned)__cvta_generic_to_shared(sAl);
    unsigned bBaseH = (unsigned)__cvta_generic_to_shared(sBh);
    unsigned bBaseL = (unsigned)__cvta_generic_to_shared(sBl);

    int aRow = wm * 32 + (lane & 15);
    unsigned aOff = (unsigned)((aRow * SA + (lane >> 4) * 8) * 2);
    int bRow = lane & 15;
    unsigned bOff = (unsigned)((bRow * SB + wn * WN + (lane >> 4) * 8) * 2);

    // A cp.async lane mapping: idx -> row=idx>>2, q=idx&3; dst byte off = idx*16
    int arow0 = tid >> 2, aq0 = tid & 3;
    int arow1 = (tid + 256) >> 2, aq1 = (tid + 256) & 3;
    const float* aSrc0 = A + (size_t)(bm + arow0) * K + aq0 * 4;
    const float* aSrc1 = A + (size_t)(bm + arow1) * K + aq1 * 4;
    int av0 = (bm + arow0 < n) ? 16 : 0;
    int av1 = (bm + arow1 < n) ? 16 : 0;

#define ISSUE_A(ch, base)                                                          \
    {                                                                              \
        int k0_ = (ch) * BK;                                                       \
        asm volatile("cp.async.cg.shared.global [%0], [%1], 16, %2;" ::            \
                     "r"((base) + tid * 16), "l"(aSrc0 + k0_), "r"(av0));          \
        asm volatile("cp.async.cg.shared.global [%0], [%1], 16, %2;" ::            \
                     "r"((base) + (tid + 256) * 16), "l"(aSrc1 + k0_), "r"(av1));  \
        asm volatile("cp.async.commit_group;");                                    \
    }

    float4 breg[BJ];
#define LOAD_B(ch)                                                                 \
    {                                                                              \
        int k0_ = (ch) * BK;                                                       \
        _Pragma("unroll")                                                          \
        for (int j = 0; j < BJ; j++) {                                             \
            int idx = tid + 256 * j;                                               \
            if (idx < BK * BN / 4) {                                               \
                int row = idx / (BN / 4), q = idx % (BN / 4);                      \
                breg[j] = *(const float4*)(B + (size_t)(k0_ + row) * BN + q * 4);  \
            }                                                                      \
        }                                                                          \
    }

    // prologue
    ISSUE_A(0, stBase0);
    LOAD_B(0);

#pragma unroll
    for (int ch = 0; ch < K / BK; ch++) {
        int buf = ch & 1;
        if (ch + 1 < K / BK) {
            ISSUE_A(ch + 1, (buf ? stBase0 : stBase1));
            asm volatile("cp.async.wait_group 1;");
        } else {
            asm volatile("cp.async.wait_group 0;");
        }
        __syncthreads();   // prior compute finished reading bf16 buffers

        // ---- convert A stage -> bf16 hi/lo ----
#pragma unroll
        for (int j = 0; j < 2; j++) {
            int idx = tid + 256 * j;
            int row = idx >> 2, q = idx & 3;
            float4 av = *(const float4*)&stA[buf][idx * 4];
            unsigned short h0, l0, h1, l1, h2, l2, h3, l3;
            bf16split(av.x, h0, l0); bf16split(av.y, h1, l1);
            bf16split(av.z, h2, l2); bf16split(av.w, h3, l3);
            int o = row * SA + q * 4;
            sAh[o] = h0; sAh[o + 1] = h1; sAh[o + 2] = h2; sAh[o + 3] = h3;
            sAl[o] = l0; sAl[o + 1] = l1; sAl[o + 2] = l2; sAl[o + 3] = l3;
        }
        // ---- convert B regs -> bf16 hi/lo ----
#pragma unroll
        for (int j = 0; j < BJ; j++) {
            int idx = tid + 256 * j;
            if (idx < BK * BN / 4) {
                int row = idx / (BN / 4), q = idx % (BN / 4);
                unsigned short h0, l0, h1, l1, h2, l2, h3, l3;
                bf16split(breg[j].x, h0, l0); bf16split(breg[j].y, h1, l1);
                bf16split(breg[j].z, h2, l2); bf16split(breg[j].w, h3, l3);
                int o = row * SB + q * 4;
                sBh[o] = h0; sBh[o + 1] = h1; sBh[o + 2] = h2; sBh[o + 3] = h3;
                sBl[o] = l0; sBl[o + 1] = l1; sBl[o + 2] = l2; sBl[o + 3] = l3;
            }
        }
        if (ch + 1 < K / BK) LOAD_B(ch + 1);   // global loads overlap compute
        __syncthreads();

        // ---- A fragments ----
        unsigned ah[2][4], al[2][4];
#pragma unroll
        for (int mt = 0; mt < 2; mt++) {
            unsigned off = aOff + (unsigned)(mt * 16 * SA * 2);
            ldsm_x4(ah[mt], aBaseH + off);
            ldsm_x4(al[mt], aBaseL + off);
        }
        // ---- MMA over n-tile pairs ----
#pragma unroll
        for (int np = 0; np < NP; np++) {
            unsigned off = bOff + (unsigned)(np * 16 * 2);
            unsigned bh[4], bl[4];
            ldsm_x4_t(bh, bBaseH + off);
            ldsm_x4_t(bl, bBaseL + off);
#pragma unroll
            for (int mt = 0; mt < 2; mt++) {
#pragma unroll
                for (int sub = 0; sub < 2; sub++) {
                    float* d = acc[mt][np * 2 + sub];
                    mma_bf16(d, al[mt], bh[sub * 2], bh[sub * 2 + 1]);
                    mma_bf16(d, ah[mt], bl[sub * 2], bl[sub * 2 + 1]);
                    mma_bf16(d, ah[mt], bh[sub * 2], bh[sub * 2 + 1]);
                }
            }
        }
    }

    // ---- epilogue ----
    int r = lane >> 2, c2 = (lane & 3) * 2;
#pragma unroll
    for (int mt = 0; mt < 2; mt++) {
        int m0 = bm + wm * 32 + mt * 16 + r;
        int m1 = m0 + 8;
#pragma unroll
        for (int nt = 0; nt < NT; nt++) {
            int cc = wn * WN + nt * 8 + c2;
            if (m0 < n) *(float2*)(C + (size_t)m0 * BN + cc) = make_float2(acc[mt][nt][0], acc[mt][nt][1]);
            if (m1 < n) *(float2*)(C + (size_t)m1 * BN + cc) = make_float2(acc[mt][nt][2], acc[mt][nt][3]);
        }
    }
#undef ISSUE_A
#undef LOAD_B
}

// ---------------- fused normalized aggregation + bias (+relu) ----------------
// out[d] = relu( dinv[d]*( sum_s dinv[s]*h[s] + dinv[d]*h[d] ) + bias )
template <int D, bool RELU>
__global__ void k_agg(const float* __restrict__ hin, float* __restrict__ hout,
                      const float* __restrict__ dinv, const int* __restrict__ rowptr,
                      const int* __restrict__ colidx, const float* __restrict__ bias,
                      int n) {
    int warp = (blockIdx.x * blockDim.x + threadIdx.x) >> 5;
    int lane = threadIdx.x & 31;
    if (warp >= n) return;
    float di = dinv[warp];

    if constexpr (D == 128) {
        const float4* hp = (const float4*)(hin + (size_t)warp * 128) + lane;
        float4 v = *hp;
        float4 acc = make_float4(di * v.x, di * v.y, di * v.z, di * v.w);
        int beg = rowptr[warp], end = rowptr[warp + 1];
        for (int e = beg; e < end; e++) {
            int s = colidx[e];
            float ds = __ldg(&dinv[s]);
            float4 u = *((const float4*)(hin + (size_t)s * 128) + lane);
            acc.x += ds * u.x; acc.y += ds * u.y;
            acc.z += ds * u.z; acc.w += ds * u.w;
        }
        float4 bb = *((const float4*)bias + lane);
        float4 o;
        o.x = di * acc.x + bb.x; o.y = di * acc.y + bb.y;
        o.z = di * acc.z + bb.z; o.w = di * acc.w + bb.w;
        if (RELU) {
            o.x = fmaxf(o.x, 0.f); o.y = fmaxf(o.y, 0.f);
            o.z = fmaxf(o.z, 0.f); o.w = fmaxf(o.w, 0.f);
        }
        *((float4*)(hout + (size_t)warp * 128) + lane) = o;
    } else {  // D == 64
        const float2* hp = (const float2*)(hin + (size_t)warp * 64) + lane;
        float2 v = *hp;
        float2 acc = make_float2(di * v.x, di * v.y);
        int beg = rowptr[warp], end = rowptr[warp + 1];
        for (int e = beg; e < end; e++) {
            int s = colidx[e];
            float ds = __ldg(&dinv[s]);
            float2 u = *((const float2*)(hin + (size_t)s * 64) + lane);
            acc.x += ds * u.x; acc.y += ds * u.y;
        }
        float2 bb = *((const float2*)bias + lane);
        float2 o;
        o.x = di * acc.x + bb.x; o.y = di * acc.y + bb.y;
        if (RELU) { o.x = fmaxf(o.x, 0.f); o.y = fmaxf(o.y, 0.f); }
        *((float2*)(hout + (size_t)warp * 64) + lane) = o;
    }
}

// ---------------- global mean pool -------------------------------------------
__global__ void k_poolzero(float* out, int* gcnt) {
    int i = blockIdx.x * blockDim.x + threadIdx.x;
    if (i < GPOOL * DOUTP) out[i] = 0.f;
    if (i < GPOOL) gcnt[i] = 0;
}

__global__ void k_pool(const float* __restrict__ h, const int* __restrict__ batch,
                       float* out, int* gcnt, int n) {
    int idx = blockIdx.x * blockDim.x + threadIdx.x;
    int node = idx >> 6;
    int c = idx & 63;
    if (node >= n) return;
    int g = batch[node];
    atomicAdd(&out[g * DOUTP + c], h[(size_t)node * DOUTP + c]);
    if (c == 0) atomicAdd(&gcnt[g], 1);
}

__global__ void k_div(float* out, const int* __restrict__ gcnt) {
    int i = blockIdx.x * blockDim.x + threadIdx.x;
    if (i < GPOOL * DOUTP) {
        int c = gcnt[i >> 6];
        out[i] /= (float)(c > 0 ? c : 1);
    }
}

// ---------------- launch ------------------------------------------------------
extern "C" void kernel_launch(void* const* d_in, const int* in_sizes, int n_in,
                              void* d_out, int out_size) {
    const float* x     = (const float*)d_in[0];
    const int*   ei    = (const int*)d_in[1];
    const int*   batch = (const int*)d_in[2];
    const float* W1 = (const float*)d_in[3];
    const float* b1 = (const float*)d_in[4];
    const float* W2 = (const float*)d_in[5];
    const float* b2 = (const float*)d_in[6];
    const float* W3 = (const float*)d_in[7];
    const float* b3 = (const float*)d_in[8];
    float* out = (float*)d_out;

    int n = in_sizes[0] / 128;
    int E = in_sizes[1] / 2;

    float *h0, *h1, *dinv;
    int *cnt, *cur, *rowptr, *colidx, *bsum, *gcnt;
    cudaGetSymbolAddress((void**)&h0, g_h0);
    cudaGetSymbolAddress((void**)&h1, g_h1);
    cudaGetSymbolAddress((void**)&dinv, g_dinv);
    cudaGetSymbolAddress((void**)&cnt, g_cnt);
    cudaGetSymbolAddress((void**)&cur, g_cur);
    cudaGetSymbolAddress((void**)&rowptr, g_rowptr);
    cudaGetSymbolAddress((void**)&colidx, g_colidx);
    cudaGetSymbolAddress((void**)&bsum, g_bsum);
    cudaGetSymbolAddress((void**)&gcnt, g_gcnt);

    int nchunk = (n + CHUNK - 1) / CHUNK;
    int mma_grid = (n + 127) / 128;
    int agg_grid = (n + 7) / 8;  // 8 warps / block

    // ---- CSR build ----
    k_zero<<<(n + 255) / 256, 256>>>(cnt, cur, n);
    k_count<<<(E + 255) / 256, 256>>>(ei, cnt, E);
    k_chunkscan<<<nchunk, CHUNK>>>(cnt, rowptr, bsum, dinv, n);
    k_mma<128><<<mma_grid, 256>>>(x, W1, h0, n);          // layer-1 transform
    k_bscan<<<1, MAXCHUNK>>>(bsum, nchunk, rowptr, n);
    k_addoff<<<(n + 255) / 256, 256>>>(rowptr, bsum, n);
    k_fill<<<(E + 255) / 256, 256>>>(ei, cur, rowptr, colidx, E);

    // ---- layer 1 agg ----
    k_agg<128, true><<<agg_grid, 256>>>(h0, h1, dinv, rowptr, colidx, b1, n);
    // ---- layer 2 ----
    k_mma<128><<<mma_grid, 256>>>(h1, W2, h0, n);
    k_agg<128, true><<<agg_grid, 256>>>(h0, h1, dinv, rowptr, colidx, b2, n);
    // ---- layer 3 ----
    k_mma<64><<<mma_grid, 256>>>(h1, W3, h0, n);
    k_agg<64, false><<<agg_grid, 256>>>(h0, h1, dinv, rowptr, colidx, b3, n);

    // ---- global mean pool ----
    k_poolzero<<<(GPOOL * DOUTP + 255) / 256, 256>>>(out, gcnt);
    k_pool<<<((size_t)n * 64 + 255) / 256, 256>>>(h1, batch, out, gcnt, n);
    k_div<<<(GPOOL * DOUTP + 255) / 256, 256>>>(out, gcnt);
}